// round 13
// baseline (speedup 1.0000x reference)
#include <cuda_runtime.h>
#include <cuda_bf16.h>
#include <stdint.h>

#define B_ 8
#define L_ 1024
#define D_ 768
#define H_ 12
#define M_ (B_ * L_)

// ---------------- scratch (device globals; no allocations allowed) ----------
__device__ float g_q[M_ * D_];
__device__ float g_k[M_ * D_];
__device__ float g_v[M_ * D_];
__device__ float g_n[M_ * D_];
__device__ float g_enh[(long)B_ * L_ * L_];

#define BFARR(name, sz) __device__ __align__(16) __nv_bfloat16 name[sz]
// split external inputs
BFARR(s_qih, M_ * D_); BFARR(s_qil, M_ * D_);
BFARR(s_kih, M_ * D_); BFARR(s_kil, M_ * D_);
BFARR(s_vih, M_ * D_); BFARR(s_vil, M_ * D_);
BFARR(s_nih, M_ * D_); BFARR(s_nil, M_ * D_);
BFARR(s_wqh, D_ * D_); BFARR(s_wql, D_ * D_);
BFARR(s_wkh, D_ * D_); BFARR(s_wkl, D_ * D_);
BFARR(s_wvh, D_ * D_); BFARR(s_wvl, D_ * D_);
BFARR(s_wnh, D_ * D_); BFARR(s_wnl, D_ * D_);
BFARR(s_woh, D_ * D_); BFARR(s_wol, D_ * D_);
// split intermediates
BFARR(g_qh, M_ * D_);  BFARR(g_ql, M_ * D_);
BFARR(g_kh, M_ * D_);  BFARR(g_kl, M_ * D_);
BFARR(g_nkTh, B_ * D_ * L_); BFARR(g_nkTl, B_ * D_ * L_);
BFARR(g_Gh, B_ * D_ * D_);   BFARR(g_Gl, B_ * D_ * D_);
BFARR(g_Th, M_ * D_);  BFARR(g_Tl, M_ * D_);
BFARR(g_ath, M_ * D_); BFARR(g_atl, M_ * D_);

// ---------------- helpers ----------------------------------------------------
__device__ __forceinline__ uint32_t smem_u32(const void* p) {
    uint32_t a;
    asm("{ .reg .u64 t; cvta.to.shared.u64 t, %1; cvt.u32.u64 %0, t; }"
        : "=r"(a) : "l"(p));
    return a;
}
__device__ __forceinline__ uint32_t f2tf32(float x) {
    uint32_t r;
    asm("cvt.rna.tf32.f32 %0, %1;" : "=r"(r) : "f"(x));
    return r;
}
__device__ __forceinline__ uint4 hi4(float4 a) {
    uint4 h;
    h.x = f2tf32(a.x); h.y = f2tf32(a.y);
    h.z = f2tf32(a.z); h.w = f2tf32(a.w);
    return h;
}
__device__ __forceinline__ void ldsm4(uint32_t* r, uint32_t addr) {
    asm volatile("ldmatrix.sync.aligned.m8n8.x4.shared.b16 {%0,%1,%2,%3}, [%4];"
                 : "=r"(r[0]), "=r"(r[1]), "=r"(r[2]), "=r"(r[3]) : "r"(addr));
}
__device__ __forceinline__ void mma8(float* d, const uint32_t* a, const uint32_t* b) {
    asm volatile(
        "mma.sync.aligned.m16n8k8.row.col.f32.tf32.tf32.f32 "
        "{%0,%1,%2,%3}, {%4,%5,%6,%7}, {%8,%9}, {%0,%1,%2,%3};"
        : "+f"(d[0]), "+f"(d[1]), "+f"(d[2]), "+f"(d[3])
        : "r"(a[0]), "r"(a[1]), "r"(a[2]), "r"(a[3]), "r"(b[0]), "r"(b[1]));
}
__device__ __forceinline__ void mma16(float* d, const uint32_t* a, const uint32_t* b) {
    asm volatile(
        "mma.sync.aligned.m16n8k16.row.col.f32.bf16.bf16.f32 "
        "{%0,%1,%2,%3}, {%4,%5,%6,%7}, {%8,%9}, {%0,%1,%2,%3};"
        : "+f"(d[0]), "+f"(d[1]), "+f"(d[2]), "+f"(d[3])
        : "r"(a[0]), "r"(a[1]), "r"(a[2]), "r"(a[3]), "r"(b[0]), "r"(b[1]));
}
__device__ __forceinline__ uint16_t bfbits(__nv_bfloat16 x) {
    return *reinterpret_cast<uint16_t*>(&x);
}
// split 4 floats -> hi(uint2), lo(uint2) packed bf16x2
__device__ __forceinline__ void splitbf4(float4 a, uint2& h, uint2& l) {
    float e[4] = {a.x, a.y, a.z, a.w};
    uint16_t hh[4], ll[4];
#pragma unroll
    for (int i = 0; i < 4; i++) {
        __nv_bfloat16 bh = __float2bfloat16_rn(e[i]);
        float hf = __bfloat162float(bh);
        __nv_bfloat16 bl = __float2bfloat16_rn(e[i] - hf);
        hh[i] = bfbits(bh);
        ll[i] = bfbits(bl);
    }
    h.x = (uint32_t)hh[0] | ((uint32_t)hh[1] << 16);
    h.y = (uint32_t)hh[2] | ((uint32_t)hh[3] << 16);
    l.x = (uint32_t)ll[0] | ((uint32_t)ll[1] << 16);
    l.y = (uint32_t)ll[2] | ((uint32_t)ll[3] << 16);
}
__device__ __forceinline__ void pack_hl(float a, float b, uint32_t& h, uint32_t& l) {
    __nv_bfloat16 ha = __float2bfloat16_rn(a);
    __nv_bfloat16 hb = __float2bfloat16_rn(b);
    __nv_bfloat16 la = __float2bfloat16_rn(a - __bfloat162float(ha));
    __nv_bfloat16 lb = __float2bfloat16_rn(b - __bfloat162float(hb));
    h = (uint32_t)bfbits(ha) | ((uint32_t)bfbits(hb) << 16);
    l = (uint32_t)bfbits(la) | ((uint32_t)bfbits(lb) << 16);
}
// cp.async
__device__ __forceinline__ void cpa16(uint32_t d, const void* s) {
    asm volatile("cp.async.cg.shared.global [%0], [%1], 16;" :: "r"(d), "l"(s));
}
__device__ __forceinline__ void cpa_commit() {
    asm volatile("cp.async.commit_group;" ::: "memory");
}
__device__ __forceinline__ void cpa_wait1() {
    asm volatile("cp.async.wait_group 1;" ::: "memory");
}

// ---------------------------------------------------------------------------
// bf16x3 GEMM core v2: pre-split operands, cp.async 3-stage pipeline.
// C[m,n] = sum_k A[m,k]*B[n,k] (+bias[n]); A,B given as bf16 hi/lo pairs.
// CTA 128x128, K-chunk 32, 8 warps (2m x 4n), warp 64x32, mma.m16n8k16.
// Stage = Ah/Al/Bh/Bl, each 128 rows x 64B, 16B-chunk XOR swizzle
//   off(r,j) = r*64 + (j ^ ((r>>1)&3))*16   (conflict-free cp.async + ldsm).
// smem = 3 stages x 32KB = 96KB -> 2 CTAs/SM. One barrier per chunk.
// ---------------------------------------------------------------------------
#define ST_AR 8192
#define ST_BY 32768
#define SMEM_G (3 * ST_BY)

__device__ __forceinline__ void bf_core2(
    const __nv_bfloat16* __restrict__ Ah, const __nv_bfloat16* __restrict__ Al,
    const __nv_bfloat16* __restrict__ Bh, const __nv_bfloat16* __restrict__ Bl,
    float* Cf, __nv_bfloat16* Chi, __nv_bfloat16* Clo,
    const float* bias, int N, int K, char* smc)
{
    const uint32_t smb = smem_u32(smc);
    const int tid = threadIdx.x;
    const int lane = tid & 31;
    const int warp = tid >> 5;
    const int wm = warp >> 2, wn = warp & 3;
    const int bm = blockIdx.y * 128, bn = blockIdx.x * 128;

    // ---- cp.async mapping: thread covers rows (tid>>2, tid>>2+64), chunk tid&3
    const int cr = tid >> 2;
    const int cjj = tid & 3;
    const uint32_t swz = (uint32_t)((cjj ^ ((cr >> 1) & 3)) * 16);
    const uint32_t sd0 = (uint32_t)cr * 64 + swz;
    const uint32_t sd1 = sd0 + 64 * 64;          // row+64: same bits 1-2
    const __nv_bfloat16* gAh = Ah + (long)(bm + cr) * K + cjj * 8;
    const __nv_bfloat16* gAl = Al + (long)(bm + cr) * K + cjj * 8;
    const __nv_bfloat16* gBh = Bh + (long)(bn + cr) * K + cjj * 8;
    const __nv_bfloat16* gBl = Bl + (long)(bn + cr) * K + cjj * 8;
    const long rK64 = (long)64 * K;

#define ISSUE(cc, st) do {                                        \
    const uint32_t sb_ = smb + (uint32_t)(st) * ST_BY;            \
    const long ko_ = (long)(cc) * 32;                             \
    cpa16(sb_ + sd0,              gAh + ko_);                     \
    cpa16(sb_ + sd1,              gAh + ko_ + rK64);              \
    cpa16(sb_ + ST_AR + sd0,      gAl + ko_);                     \
    cpa16(sb_ + ST_AR + sd1,      gAl + ko_ + rK64);              \
    cpa16(sb_ + 2 * ST_AR + sd0,  gBh + ko_);                     \
    cpa16(sb_ + 2 * ST_AR + sd1,  gBh + ko_ + rK64);              \
    cpa16(sb_ + 3 * ST_AR + sd0,  gBl + ko_);                     \
    cpa16(sb_ + 3 * ST_AR + sd1,  gBl + ko_ + rK64);              \
} while (0)

    // ---- ldsm address constants
    const int r4 = lane & 15;
    const uint32_t xa = ((uint32_t)(r4 >> 1)) & 3;
    const uint32_t h16 = (uint32_t)(lane & 16) >> 4;
    const uint32_t caof0 = ((0 + h16) ^ xa) * 16;   // s=0
    const uint32_t caof1 = ((2 + h16) ^ xa) * 16;   // s=1
    const uint32_t aRow = (uint32_t)(wm * 64 + r4) * 64;

    const int r8 = (lane & 7) + ((lane & 16) >> 1); // 0..15
    const uint32_t xb = ((uint32_t)((lane & 7) >> 1)) & 3;
    const uint32_t hb8 = (uint32_t)(lane & 8) >> 3;
    const uint32_t cbof0 = ((0 + hb8) ^ xb) * 16;
    const uint32_t cbof1 = ((2 + hb8) ^ xb) * 16;
    const uint32_t bRow = (uint32_t)(wn * 32 + r8) * 64;

    float acc[4][4][4];
#pragma unroll
    for (int m = 0; m < 4; m++)
#pragma unroll
        for (int n = 0; n < 4; n++)
#pragma unroll
            for (int r = 0; r < 4; r++) acc[m][n][r] = 0.f;

    const int NC = K >> 5;
    ISSUE(0, 0); cpa_commit();
    ISSUE(1, 1); cpa_commit();

    int stg = 0;
    for (int c = 0; c < NC; c++) {
        cpa_wait1();          // chunk c landed (this thread)
        __syncthreads();      // all threads' chunk c visible; all done MMA(c-1)
        if (c + 2 < NC) {
            const int ws = (stg + 2 >= 3) ? stg - 1 : stg + 2;
            ISSUE(c + 2, ws);
        }
        cpa_commit();

        const uint32_t sb = smb + (uint32_t)stg * ST_BY;
#pragma unroll
        for (int s = 0; s < 2; s++) {
            const uint32_t ca = s ? caof1 : caof0;
            const uint32_t cb = s ? cbof1 : cbof0;
            uint32_t bh[8], bl[8], af[16];
            const uint32_t bb = sb + 2 * ST_AR + bRow + cb;
            ldsm4(bh + 0, bb);
            ldsm4(bh + 4, bb + 16 * 64);
            ldsm4(bl + 0, bb + ST_AR);
            ldsm4(bl + 4, bb + ST_AR + 16 * 64);
            const uint32_t ab = sb + aRow + ca;
#pragma unroll
            for (int m = 0; m < 4; m++) ldsm4(af + 4 * m, ab + m * (16 * 64));
#pragma unroll
            for (int m = 0; m < 4; m++)
#pragma unroll
                for (int n = 0; n < 4; n++)
                    mma16(acc[m][n], af + 4 * m, bh + 2 * n);
#pragma unroll
            for (int m = 0; m < 4; m++)
#pragma unroll
                for (int n = 0; n < 4; n++)
                    mma16(acc[m][n], af + 4 * m, bl + 2 * n);
#pragma unroll
            for (int m = 0; m < 4; m++)
                ldsm4(af + 4 * m, ab + ST_AR + m * (16 * 64));
#pragma unroll
            for (int m = 0; m < 4; m++)
#pragma unroll
                for (int n = 0; n < 4; n++)
                    mma16(acc[m][n], af + 4 * m, bh + 2 * n);
        }
        stg++; if (stg == 3) stg = 0;
    }
#undef ISSUE

    const int g = lane >> 2;
    const int t = lane & 3;
#pragma unroll
    for (int n = 0; n < 4; n++) {
        const int col = bn + wn * 32 + n * 8 + t * 2;
        float b0 = 0.f, b1 = 0.f;
        if (bias) { b0 = bias[col]; b1 = bias[col + 1]; }
#pragma unroll
        for (int m = 0; m < 4; m++) {
            const long r0 = bm + wm * 64 + m * 16 + g;
            const float v00 = acc[m][n][0] + b0, v01 = acc[m][n][1] + b1;
            const float v10 = acc[m][n][2] + b0, v11 = acc[m][n][3] + b1;
            if (Cf) {
                *(float2*)(Cf + r0 * N + col) = make_float2(v00, v01);
                *(float2*)(Cf + (r0 + 8) * N + col) = make_float2(v10, v11);
            }
            if (Chi) {
                uint32_t h, l;
                pack_hl(v00, v01, h, l);
                *(uint32_t*)(Chi + r0 * N + col) = h;
                *(uint32_t*)(Clo + r0 * N + col) = l;
                pack_hl(v10, v11, h, l);
                *(uint32_t*)(Chi + (r0 + 8) * N + col) = h;
                *(uint32_t*)(Clo + (r0 + 8) * N + col) = l;
            }
        }
    }
}

__global__ void __launch_bounds__(256, 2) tc_gemm2(
    const __nv_bfloat16* Ah, const __nv_bfloat16* Al,
    const __nv_bfloat16* Bh, const __nv_bfloat16* Bl,
    float* Cf, __nv_bfloat16* Chi, __nv_bfloat16* Clo,
    const float* bias, int N, int K, long sA, long sB, long sC)
{
    extern __shared__ char smc[];
    const long z = blockIdx.z;
    bf_core2(Ah + z * sA, Al + z * sA, Bh + z * sB, Bl + z * sB,
             Cf ? Cf + z * sC : nullptr,
             Chi ? Chi + z * sC : nullptr,
             Clo ? Clo + z * sC : nullptr,
             bias, N, K, smc);
}

// Merged projections: z selects operand set. outh/outl may be null.
struct Proj2 {
    const __nv_bfloat16 *inh[4], *inl[4], *Wh[4], *Wl[4];
    const float* bias[4];
    float* outf[4];
    __nv_bfloat16 *outh[4], *outl[4];
};

__global__ void __launch_bounds__(256, 2) tc_proj2(Proj2 p)
{
    extern __shared__ char smc[];
    const int z = blockIdx.z;
    bf_core2(p.inh[z], p.inl[z], p.Wh[z], p.Wl[z],
             p.outf[z], p.outh[z], p.outl[z], p.bias[z], D_, D_, smc);
}

// ---------------------------------------------------------------------------
// Batched elementwise split fp32 -> bf16 hi/lo (up to 5 tensors via grid.y).
// ---------------------------------------------------------------------------
struct SplitArgs {
    const float* in[5];
    __nv_bfloat16 *hi[5], *lo[5];
};

__global__ void split_bf(SplitArgs s, int n4)
{
    const int z = blockIdx.y;
    const long i = (long)blockIdx.x * 256 + threadIdx.x;
    if (i >= n4) return;
    float4 v = ((const float4*)s.in[z])[i];
    uint2 h, l;
    splitbf4(v, h, l);
    ((uint2*)s.hi[z])[i] = h;
    ((uint2*)s.lo[z])[i] = l;
}

// ---------------------------------------------------------------------------
// Batched transpose + split: in fp32 [B][L][D] -> out bf16 hi/lo [B][D][L]
// ---------------------------------------------------------------------------
__global__ void transpose_split(const float* __restrict__ in,
                                __nv_bfloat16* __restrict__ oh,
                                __nv_bfloat16* __restrict__ ol)
{
    __shared__ float tle[32][33];
    const int b = blockIdx.z;
    const int d0 = blockIdx.x * 32;
    const int l0 = blockIdx.y * 32;
    const int x = threadIdx.x;
    const int y = threadIdx.y;
    const float* ib = in + ((long)b * L_ + l0) * D_ + d0;
#pragma unroll
    for (int i = y; i < 32; i += 8) tle[i][x] = ib[(long)i * D_ + x];
    __syncthreads();
    const long ob = ((long)b * D_ + d0) * L_ + l0;
#pragma unroll
    for (int i = y; i < 32; i += 8) {
        float v = tle[x][i];
        __nv_bfloat16 h = __float2bfloat16_rn(v);
        __nv_bfloat16 l = __float2bfloat16_rn(v - __bfloat162float(h));
        oh[ob + (long)i * L_ + x] = h;
        ol[ob + (long)i * L_ + x] = l;
    }
}

// ---------------------------------------------------------------------------
// Fused attention (validated R6-R12); epilogue now emits bf16 hi/lo att.
// ---------------------------------------------------------------------------
__global__ void __launch_bounds__(256, 2) attn_mma(
    const float* __restrict__ Q, const float* __restrict__ K,
    const float* __restrict__ V, const float* __restrict__ E,
    __nv_bfloat16* __restrict__ Oh, __nv_bfloat16* __restrict__ Ol)
{
    extern __shared__ float sh[];
    float* sQ = sh;
    float* sK = sh + 128 * 68;
    float* sVh = sK + 64 * 68;

    const int b = blockIdx.y / H_;
    const int h = blockIdx.y % H_;
    const int l0 = blockIdx.x * 128;
    const int tid = threadIdx.x;
    const int lane = tid & 31;
    const int w = tid >> 5;
    const int g = lane >> 2;
    const int t = lane & 3;

    const float* qb = Q + ((long)b * L_ + l0) * D_ + h * 64;
    const float* kb = K + (long)b * L_ * D_ + h * 64;
    const float* vb = V + (long)b * L_ * D_ + h * 64;
    const float* e0 = E + ((long)b * L_ + l0 + w * 16 + g) * L_;
    const float* e1 = e0 + 8 * L_;

#pragma unroll
    for (int it = 0; it < 8; it++) {
        int f = tid + it * 256;
        int row = f >> 4;
        int d4 = (f & 15) << 2;
        float4 v = *(const float4*)(qb + (long)row * D_ + d4);
        *(uint4*)(sQ + row * 68 + d4) = hi4(v);
    }

    const uint32_t sQa = smem_u32(sQ) +
        ((((uint32_t)(w * 16 + (lane & 15)) * 68u) + ((lane & 16) >> 2)) << 2);
    const uint32_t bPat =
        ((((uint32_t)((lane & 7) + ((lane & 16) >> 1)) * 68u) +
          ((lane & 8) >> 1)) << 2);
    const uint32_t sKa = smem_u32(sK) + bPat;
    const uint32_t sVha = smem_u32(sVh) + bPat;
    const uint32_t R16 = (16 * 68) << 2;

    float o[8][4];
#pragma unroll
    for (int j = 0; j < 8; j++)
#pragma unroll
        for (int r = 0; r < 4; r++) o[j][r] = 0.f;
    float m0 = -1e30f, m1 = -1e30f, sum0 = 0.f, sum1 = 0.f;

    for (int jb = 0; jb < 16; jb++) {
        __syncthreads();
#pragma unroll
        for (int it = 0; it < 4; it++) {
            int f = tid + it * 256;
            int key = f >> 4;
            int d4 = (f & 15) << 2;
            float4 v = *(const float4*)(kb + (long)(jb * 64 + key) * D_ + d4);
            *(uint4*)(sK + key * 68 + d4) = hi4(v);
        }
#pragma unroll
        for (int it = 0; it < 4; it++) {
            int f = tid + it * 256;
            int key = f >> 4;
            int d4 = (f & 15) << 2;
            float4 v = *(const float4*)(vb + (long)(jb * 64 + key) * D_ + d4);
            float vv[4] = {v.x, v.y, v.z, v.w};
#pragma unroll
            for (int i = 0; i < 4; i++)
                *(uint32_t*)(sVh + (d4 + i) * 68 + key) = f2tf32(vv[i]);
        }
        __syncthreads();

        float accS[8][4];
#pragma unroll
        for (int j = 0; j < 8; j++)
#pragma unroll
            for (int r = 0; r < 4; r++) accS[j][r] = 0.f;
#pragma unroll
        for (int s = 0; s < 8; s++) {
            const uint32_t ks = (uint32_t)s * 32;
            uint32_t af[4], bf[16];
            ldsm4(af, sQa + ks);
            ldsm4(bf + 0,  sKa + ks);
            ldsm4(bf + 4,  sKa + ks + R16);
            ldsm4(bf + 8,  sKa + ks + 2 * R16);
            ldsm4(bf + 12, sKa + ks + 3 * R16);
#pragma unroll
            for (int j = 0; j < 8; j++) mma8(accS[j], af, bf + 2 * j);
        }

#pragma unroll
        for (int j = 0; j < 8; j++) {
            const int col = jb * 64 + 8 * j + 2 * t;
            float2 ea = *(const float2*)(e0 + col);
            float2 ebv = *(const float2*)(e1 + col);
            accS[j][0] = (accS[j][0] + ea.x) * 0.0625f;
            accS[j][1] = (accS[j][1] + ea.y) * 0.0625f;
            accS[j][2] = (accS[j][2] + ebv.x) * 0.0625f;
            accS[j][3] = (accS[j][3] + ebv.y) * 0.0625f;
        }

        float mx0 = -1e30f, mx1 = -1e30f;
#pragma unroll
        for (int j = 0; j < 8; j++) {
            mx0 = fmaxf(mx0, fmaxf(accS[j][0], accS[j][1]));
            mx1 = fmaxf(mx1, fmaxf(accS[j][2], accS[j][3]));
        }
#pragma unroll
        for (int off = 1; off <= 2; off <<= 1) {
            mx0 = fmaxf(mx0, __shfl_xor_sync(0xffffffffu, mx0, off));
            mx1 = fmaxf(mx1, __shfl_xor_sync(0xffffffffu, mx1, off));
        }
        const float nm0 = fmaxf(m0, mx0), nm1 = fmaxf(m1, mx1);
        const float sc0 = __expf(m0 - nm0), sc1 = __expf(m1 - nm1);
        float rs0 = 0.f, rs1 = 0.f;
#pragma unroll
        for (int j = 0; j < 8; j++) {
            accS[j][0] = __expf(accS[j][0] - nm0);
            accS[j][1] = __expf(accS[j][1] - nm0);
            accS[j][2] = __expf(accS[j][2] - nm1);
            accS[j][3] = __expf(accS[j][3] - nm1);
            rs0 += accS[j][0] + accS[j][1];
            rs1 += accS[j][2] + accS[j][3];
        }
#pragma unroll
        for (int off = 1; off <= 2; off <<= 1) {
            rs0 += __shfl_xor_sync(0xffffffffu, rs0, off);
            rs1 += __shfl_xor_sync(0xffffffffu, rs1, off);
        }
        sum0 = sum0 * sc0 + rs0;
        sum1 = sum1 * sc1 + rs1;
        m0 = nm0; m1 = nm1;
#pragma unroll
        for (int j = 0; j < 8; j++) {
            o[j][0] *= sc0; o[j][1] *= sc0;
            o[j][2] *= sc1; o[j][3] *= sc1;
        }

        const int sl0 = (lane & ~3) | (t >> 1);
        const int sl2 = sl0 + 2;
#pragma unroll
        for (int kt = 0; kt < 8; kt++) {
            float p00 = __shfl_sync(0xffffffffu, accS[kt][0], sl0);
            float p01 = __shfl_sync(0xffffffffu, accS[kt][1], sl0);
            float p20 = __shfl_sync(0xffffffffu, accS[kt][0], sl2);
            float p21 = __shfl_sync(0xffffffffu, accS[kt][1], sl2);
            float p10 = __shfl_sync(0xffffffffu, accS[kt][2], sl0);
            float p11 = __shfl_sync(0xffffffffu, accS[kt][3], sl0);
            float p30 = __shfl_sync(0xffffffffu, accS[kt][2], sl2);
            float p31 = __shfl_sync(0xffffffffu, accS[kt][3], sl2);
            float a0 = (t & 1) ? p01 : p00;
            float a1 = (t & 1) ? p11 : p10;
            float a2 = (t & 1) ? p21 : p20;
            float a3 = (t & 1) ? p31 : p30;
            uint32_t ah[4];
            ah[0] = f2tf32(a0); ah[1] = f2tf32(a1);
            ah[2] = f2tf32(a2); ah[3] = f2tf32(a3);

            const uint32_t ks = (uint32_t)kt * 32;
            uint32_t bvr[16];
            ldsm4(bvr + 0,  sVha + ks);
            ldsm4(bvr + 4,  sVha + ks + R16);
            ldsm4(bvr + 8,  sVha + ks + 2 * R16);
            ldsm4(bvr + 12, sVha + ks + 3 * R16);
#pragma unroll
            for (int j = 0; j < 8; j++)
                mma8(o[j], ah, bvr + 2 * j);
        }
    }

    const float inv0 = 1.f / sum0, inv1 = 1.f / sum1;
    const long obase = ((long)b * L_ + l0 + w * 16) * D_ + h * 64;
#pragma unroll
    for (int j = 0; j < 8; j++) {
        const int col = 8 * j + 2 * t;
        uint32_t hh, ll;
        pack_hl(o[j][0] * inv0, o[j][1] * inv0, hh, ll);
        *(uint32_t*)(Oh + obase + (long)g * D_ + col) = hh;
        *(uint32_t*)(Ol + obase + (long)g * D_ + col) = ll;
        pack_hl(o[j][2] * inv1, o[j][3] * inv1, hh, ll);
        *(uint32_t*)(Oh + obase + (long)(g + 8) * D_ + col) = hh;
        *(uint32_t*)(Ol + obase + (long)(g + 8) * D_ + col) = ll;
    }
}

// ---------------------------------------------------------------------------
extern "C" void kernel_launch(void* const* d_in, const int* in_sizes, int n_in,
                              void* d_out, int out_size)
{
    const float* query = (const float*)d_in[0];
    const float* key   = (const float*)d_in[1];
    const float* value = (const float*)d_in[2];
    const float* news  = (const float*)d_in[3];
    const float* Wq = (const float*)d_in[4];
    const float* bq = (const float*)d_in[5];
    const float* Wk = (const float*)d_in[6];
    const float* bk = (const float*)d_in[7];
    const float* Wv = (const float*)d_in[8];
    const float* bv = (const float*)d_in[9];
    const float* Wn = (const float*)d_in[10];
    const float* bn = (const float*)d_in[11];
    const float* Wo = (const float*)d_in[12];
    const float* bo = (const float*)d_in[13];
    // d_in[14] = pos. Mathematically irrelevant (swapaxes of swapped enh == enh).

#define SYM(v, s) cudaGetSymbolAddress((void**)&v, s)
    float *pq, *pk, *pv, *pn, *penh;
    SYM(pq, g_q); SYM(pk, g_k); SYM(pv, g_v); SYM(pn, g_n); SYM(penh, g_enh);
    __nv_bfloat16 *qih, *qil, *kih, *kil, *vih, *vil, *nih, *nil;
    SYM(qih, s_qih); SYM(qil, s_qil); SYM(kih, s_kih); SYM(kil, s_kil);
    SYM(vih, s_vih); SYM(vil, s_vil); SYM(nih, s_nih); SYM(nil, s_nil);
    __nv_bfloat16 *wqh, *wql, *wkh, *wkl, *wvh, *wvl, *wnh, *wnl, *woh, *wol;
    SYM(wqh, s_wqh); SYM(wql, s_wql); SYM(wkh, s_wkh); SYM(wkl, s_wkl);
    SYM(wvh, s_wvh); SYM(wvl, s_wvl); SYM(wnh, s_wnh); SYM(wnl, s_wnl);
    SYM(woh, s_woh); SYM(wol, s_wol);
    __nv_bfloat16 *qh, *ql, *kh, *kl, *nkTh, *nkTl, *Gh, *Gl, *Th, *Tl, *ath, *atl;
    SYM(qh, g_qh); SYM(ql, g_ql); SYM(kh, g_kh); SYM(kl, g_kl);
    SYM(nkTh, g_nkTh); SYM(nkTl, g_nkTl); SYM(Gh, g_Gh); SYM(Gl, g_Gl);
    SYM(Th, g_Th); SYM(Tl, g_Tl); SYM(ath, g_ath); SYM(atl, g_atl);
#undef SYM

    dim3 blk(256);
    cudaFuncSetAttribute(tc_proj2, cudaFuncAttributeMaxDynamicSharedMemorySize, SMEM_G);
    cudaFuncSetAttribute(tc_gemm2, cudaFuncAttributeMaxDynamicSharedMemorySize, SMEM_G);

    // 1. split external inputs
    SplitArgs sa;
    sa.in[0] = query; sa.hi[0] = qih; sa.lo[0] = qil;
    sa.in[1] = key;   sa.hi[1] = kih; sa.lo[1] = kil;
    sa.in[2] = value; sa.hi[2] = vih; sa.lo[2] = vil;
    sa.in[3] = news;  sa.hi[3] = nih; sa.lo[3] = nil;
    sa.in[4] = query; sa.hi[4] = qih; sa.lo[4] = qil;  // unused slot
    split_bf<<<dim3(M_ * D_ / 4 / 256, 4), blk>>>(sa, M_ * D_ / 4);
    SplitArgs sw;
    sw.in[0] = Wq; sw.hi[0] = wqh; sw.lo[0] = wql;
    sw.in[1] = Wk; sw.hi[1] = wkh; sw.lo[1] = wkl;
    sw.in[2] = Wv; sw.hi[2] = wvh; sw.lo[2] = wvl;
    sw.in[3] = Wn; sw.hi[3] = wnh; sw.lo[3] = wnl;
    sw.in[4] = Wo; sw.hi[4] = woh; sw.lo[4] = wol;
    split_bf<<<dim3(D_ * D_ / 4 / 256, 5), blk>>>(sw, D_ * D_ / 4);

    // 2. projections (q,k also emit bf16 hi/lo for the chain GEMMs)
    Proj2 pr;
    pr.inh[0] = qih; pr.inl[0] = qil; pr.Wh[0] = wqh; pr.Wl[0] = wql;
    pr.bias[0] = bq; pr.outf[0] = pq; pr.outh[0] = qh; pr.outl[0] = ql;
    pr.inh[1] = kih; pr.inl[1] = kil; pr.Wh[1] = wkh; pr.Wl[1] = wkl;
    pr.bias[1] = bk; pr.outf[1] = pk; pr.outh[1] = kh; pr.outl[1] = kl;
    pr.inh[2] = vih; pr.inl[2] = vil; pr.Wh[2] = wvh; pr.Wl[2] = wvl;
    pr.bias[2] = bv; pr.outf[2] = pv; pr.outh[2] = nullptr; pr.outl[2] = nullptr;
    pr.inh[3] = nih; pr.inl[3] = nil; pr.Wh[3] = wnh; pr.Wl[3] = wnl;
    pr.bias[3] = bn; pr.outf[3] = pn; pr.outh[3] = nullptr; pr.outl[3] = nullptr;
    tc_proj2<<<dim3(D_ / 128, M_ / 128, 4), blk, SMEM_G>>>(pr);

    // 3. enh = q (nk^T nk) k^T chain
    transpose_split<<<dim3(D_ / 32, L_ / 32, B_), dim3(32, 8)>>>(pn, nkTh, nkTl);
    tc_gemm2<<<dim3(D_ / 128, D_ / 128, B_), blk, SMEM_G>>>(
        nkTh, nkTl, nkTh, nkTl, nullptr, Gh, Gl, nullptr,
        D_, L_, (long)D_ * L_, (long)D_ * L_, (long)D_ * D_);
    tc_gemm2<<<dim3(D_ / 128, L_ / 128, B_), blk, SMEM_G>>>(
        qh, ql, Gh, Gl, nullptr, Th, Tl, nullptr,
        D_, D_, (long)L_ * D_, (long)D_ * D_, (long)L_ * D_);
    tc_gemm2<<<dim3(L_ / 128, L_ / 128, B_), blk, SMEM_G>>>(
        Th, Tl, kh, kl, penh, nullptr, nullptr, nullptr,
        L_, D_, (long)L_ * D_, (long)L_ * D_, (long)L_ * L_);

    // 4. fused attention (writes att as bf16 hi/lo)
    const int attn_smem = (128 * 68 + 2 * 64 * 68) * 4;  // 69632
    cudaFuncSetAttribute(attn_mma, cudaFuncAttributeMaxDynamicSharedMemorySize,
                         attn_smem);
    attn_mma<<<dim3(L_ / 128, B_ * H_), blk, attn_smem>>>(pq, pk, pv, penh, ath, atl);

    // 5. output projection -> d_out
    tc_gemm2<<<dim3(D_ / 128, M_ / 128, 1), blk, SMEM_G>>>(
        ath, atl, woh, wol, (float*)d_out, nullptr, nullptr, bo,
        D_, D_, 0, 0, 0);
}